// round 14
// baseline (speedup 1.0000x reference)
#include <cuda_runtime.h>
#include <cstdint>

#define C0  0.28209479177387814f
#define C1  0.4886025119029199f
#define C2_0  1.0925484305920792f
#define C2_1 (-1.0925484305920792f)
#define C2_2  0.31539156525252005f
#define C2_3 (-1.0925484305920792f)
#define C2_4  0.5462742152960396f
#define C3_0 (-0.5900435899266435f)
#define C3_1  2.890611442640554f
#define C3_2 (-0.4570457994644658f)
#define C3_3  0.3731763325901154f
#define C3_4 (-0.4570457994644658f)
#define C3_5  1.445305721320277f
#define C3_6 (-0.5900435899266435f)

#define BLK 256
#define FR_FLOATS (BLK * 45)          // 11520 floats = 45 KB
#define WARP_F4  360                  // 32 rows * 45 floats / 4 per warp

__device__ __forceinline__ uint32_t smem_u32(const void* p) {
    uint32_t a;
    asm("{ .reg .u64 t; cvta.to.shared.u64 t, %1; cvt.u32.u64 %0, t; }"
        : "=r"(a) : "l"(p));
    return a;
}

__global__ __launch_bounds__(BLK)
void gs_preprocess_kernel(const float*  __restrict__ xyz,
                          const float*  __restrict__ fdc,
                          const float*  __restrict__ frest,
                          const float*  __restrict__ scaling,
                          const float4* __restrict__ rotation,
                          const float*  __restrict__ opacity,
                          const float*  __restrict__ campos,
                          const float*  __restrict__ smod,
                          float* __restrict__ out,
                          int n)
{
    __shared__ float sbuf[FR_FLOATS];

    const int tid  = threadIdx.x;
    const int wid  = tid >> 5;
    const int lane = tid & 31;
    const int base = blockIdx.x * BLK;
    const int i    = base + tid;
    const bool full = (base + BLK <= n);
    const bool act  = (i < n);

    // ---- warp-private staging: each warp copies ONLY its own 32 rows --------
    if (full) {
        // warp chunk: rows [base + wid*32, +32), 5760 B, 16B-aligned
        const float4* g = (const float4*)(frest + ((size_t)base + wid * 32) * 45);
        const uint32_t s0 = smem_u32(sbuf + wid * (32 * 45));
        #pragma unroll
        for (int j = lane; j < WARP_F4; j += 32) {
            asm volatile("cp.async.cg.shared.global [%0], [%1], 16;"
                         :: "r"(s0 + j * 16), "l"(g + j) : "memory");
        }
        asm volatile("cp.async.commit_group;" ::: "memory");
    } else {
        const int cnt = (n - base) * 45;
        for (int j = tid; j < cnt; j += BLK)
            sbuf[j] = frest[(size_t)base * 45 + j];
    }

    // ---- front-batch scalar inputs: fly concurrently with the staging -------
    float px=0, py=0, pz=0;
    float f0=0, f1=0, f2=0;
    float sc0=0, sc1=0, sc2=0;
    float ov=0;
    float4 q = make_float4(1,0,0,0);
    if (act) {
        px  = xyz[3*i+0]; py = xyz[3*i+1]; pz = xyz[3*i+2];
        f0  = fdc[3*i+0]; f1 = fdc[3*i+1]; f2 = fdc[3*i+2];
        sc0 = scaling[3*i+0]; sc1 = scaling[3*i+1]; sc2 = scaling[3*i+2];
        ov  = opacity[i];
        q   = rotation[i];
    }
    const float cx = campos[0], cy = campos[1], cz = campos[2];
    const float mod = smod[0];

    // ---- early stores: pass-through + opacity + covariance ------------------
    // (independent of smem; overlap with the cp.async drain below)
    if (act) {
        out[3*i+0] = px; out[3*i+1] = py; out[3*i+2] = pz;
        out[(size_t)3*n + i] = 1.0f / (1.0f + expf(-ov));

        float s0 = expf(sc0) * mod;
        float s1 = expf(sc1) * mod;
        float s2 = expf(sc2) * mod;
        const float v0 = s0*s0, v1 = s1*s1, v2 = s2*s2;

        float qn = rsqrtf(q.x*q.x + q.y*q.y + q.z*q.z + q.w*q.w);
        const float w_ = q.x*qn, qx = q.y*qn, qy = q.z*qn, qz = q.w*qn;

        const float r00 = 1.0f - 2.0f*(qy*qy + qz*qz);
        const float r01 = 2.0f*(qx*qy - w_*qz);
        const float r02 = 2.0f*(qx*qz + w_*qy);
        const float r10 = 2.0f*(qx*qy + w_*qz);
        const float r11 = 1.0f - 2.0f*(qx*qx + qz*qz);
        const float r12 = 2.0f*(qy*qz - w_*qx);
        const float r20 = 2.0f*(qx*qz - w_*qy);
        const float r21 = 2.0f*(qy*qz + w_*qx);
        const float r22 = 1.0f - 2.0f*(qx*qx + qy*qy);

        const float m00 = r00*r00*v0 + r01*r01*v1 + r02*r02*v2;
        const float m01 = r00*r10*v0 + r01*r11*v1 + r02*r12*v2;
        const float m02 = r00*r20*v0 + r01*r21*v1 + r02*r22*v2;
        const float m11 = r10*r10*v0 + r11*r11*v1 + r12*r12*v2;
        const float m12 = r10*r20*v0 + r11*r21*v1 + r12*r22*v2;
        const float m22 = r20*r20*v0 + r21*r21*v1 + r22*r22*v2;

        const size_t covb = (size_t)7*n + (size_t)6*i;
        out[covb+0] = m00; out[covb+1] = m01; out[covb+2] = m02;
        out[covb+3] = m11; out[covb+4] = m12; out[covb+5] = m22;
    }

    // ---- per-warp wait: no cross-warp coupling ------------------------------
    if (full) {
        asm volatile("cp.async.wait_group 0;" ::: "memory");
        __syncwarp();
    } else {
        __syncthreads();
    }

    // ---- color (needs this warp's smem chunk only) --------------------------
    if (act) {
        float dx = px - cx, dy = py - cy, dz = pz - cz;
        float inv = rsqrtf(dx*dx + dy*dy + dz*dz);
        float x = dx * inv, y = dy * inv, z = dz * inv;

        const float xx = x*x, yy = y*y, zz = z*z;
        const float xy = x*y, yz = y*z, xz = x*z;

        float b[16];
        b[0]  = C0;
        b[1]  = -C1 * y;
        b[2]  =  C1 * z;
        b[3]  = -C1 * x;
        b[4]  = C2_0 * xy;
        b[5]  = C2_1 * yz;
        b[6]  = C2_2 * (2.0f*zz - xx - yy);
        b[7]  = C2_3 * xz;
        b[8]  = C2_4 * (xx - yy);
        b[9]  = C3_0 * y * (3.0f*xx - yy);
        b[10] = C3_1 * xy * z;
        b[11] = C3_2 * y * (4.0f*zz - xx - yy);
        b[12] = C3_3 * z * (2.0f*zz - 3.0f*xx - 3.0f*yy);
        b[13] = C3_4 * x * (4.0f*zz - xx - yy);
        b[14] = C3_5 * z * (xx - yy);
        b[15] = C3_6 * x * (xx - 3.0f*yy);

        float c0 = b[0] * f0;
        float c1 = b[0] * f1;
        float c2 = b[0] * f2;

        const float* fr = sbuf + tid * 45;   // stride 45: conflict-free
        #pragma unroll
        for (int k = 1; k < 16; ++k) {
            const float w = b[k];
            c0 = fmaf(w, fr[(k-1)*3 + 0], c0);
            c1 = fmaf(w, fr[(k-1)*3 + 1], c1);
            c2 = fmaf(w, fr[(k-1)*3 + 2], c2);
        }
        c0 = fmaxf(c0 + 0.5f, 0.0f);
        c1 = fmaxf(c1 + 0.5f, 0.0f);
        c2 = fmaxf(c2 + 0.5f, 0.0f);

        // direct stores: stride-3 across the warp = 3 fully-covered 128B lines
        const size_t colb = (size_t)4*n;
        out[colb + 3*i+0] = c0;
        out[colb + 3*i+1] = c1;
        out[colb + 3*i+2] = c2;
    }
}

extern "C" void kernel_launch(void* const* d_in, const int* in_sizes, int n_in,
                              void* d_out, int out_size) {
    const float*  xyz      = (const float*)d_in[0];
    const float*  fdc      = (const float*)d_in[1];
    const float*  frest    = (const float*)d_in[2];
    const float*  scaling  = (const float*)d_in[3];
    const float4* rotation = (const float4*)d_in[4];
    const float*  opacity  = (const float*)d_in[5];
    const float*  campos   = (const float*)d_in[6];
    const float*  smod     = (const float*)d_in[7];
    float* out = (float*)d_out;

    const int n = in_sizes[0] / 3;

    const int grid = (n + BLK - 1) / BLK;
    gs_preprocess_kernel<<<grid, BLK>>>(xyz, fdc, frest, scaling, rotation,
                                        opacity, campos, smod, out, n);
}

// round 15
// speedup vs baseline: 1.0025x; 1.0025x over previous
#include <cuda_runtime.h>
#include <cstdint>

#define C0  0.28209479177387814f
#define C1  0.4886025119029199f
#define C2_0  1.0925484305920792f
#define C2_1 (-1.0925484305920792f)
#define C2_2  0.31539156525252005f
#define C2_3 (-1.0925484305920792f)
#define C2_4  0.5462742152960396f
#define C3_0 (-0.5900435899266435f)
#define C3_1  2.890611442640554f
#define C3_2 (-0.4570457994644658f)
#define C3_3  0.3731763325901154f
#define C3_4 (-0.4570457994644658f)
#define C3_5  1.445305721320277f
#define C3_6 (-0.5900435899266435f)

#define BLK 256
#define FR_FLOATS (BLK * 45)          // 11520 floats = 45 KB
#define WARP_F4  360                  // 32 rows * 45 floats / 4 per warp

__device__ __forceinline__ uint32_t smem_u32(const void* p) {
    uint32_t a;
    asm("{ .reg .u64 t; cvta.to.shared.u64 t, %1; cvt.u32.u64 %0, t; }"
        : "=r"(a) : "l"(p));
    return a;
}

__global__ __launch_bounds__(BLK)
void gs_preprocess_kernel(const float*  __restrict__ xyz,
                          const float*  __restrict__ fdc,
                          const float*  __restrict__ frest,
                          const float*  __restrict__ scaling,
                          const float4* __restrict__ rotation,
                          const float*  __restrict__ opacity,
                          const float*  __restrict__ campos,
                          const float*  __restrict__ smod,
                          float* __restrict__ out,
                          int n)
{
    __shared__ float sbuf[FR_FLOATS];

    const int tid  = threadIdx.x;
    const int wid  = tid >> 5;
    const int lane = tid & 31;
    const int base = blockIdx.x * BLK;
    const int i    = base + tid;
    const bool full = (base + BLK <= n);
    const bool act  = (i < n);

    // ---- warp-private staging: each warp copies ONLY its own 32 rows --------
    if (full) {
        // warp chunk: rows [base + wid*32, +32), 5760 B, 16B-aligned
        const float4* g = (const float4*)(frest + ((size_t)base + wid * 32) * 45);
        const uint32_t s0 = smem_u32(sbuf + wid * (32 * 45));
        #pragma unroll
        for (int j = lane; j < WARP_F4; j += 32) {
            asm volatile("cp.async.cg.shared.global [%0], [%1], 16;"
                         :: "r"(s0 + j * 16), "l"(g + j) : "memory");
        }
        asm volatile("cp.async.commit_group;" ::: "memory");
    } else {
        const int cnt = (n - base) * 45;
        for (int j = tid; j < cnt; j += BLK)
            sbuf[j] = frest[(size_t)base * 45 + j];
    }

    // ---- front-batch scalar inputs: fly concurrently with the staging -------
    float px=0, py=0, pz=0;
    float f0=0, f1=0, f2=0;
    float sc0=0, sc1=0, sc2=0;
    float ov=0;
    float4 q = make_float4(1,0,0,0);
    if (act) {
        px  = xyz[3*i+0]; py = xyz[3*i+1]; pz = xyz[3*i+2];
        f0  = fdc[3*i+0]; f1 = fdc[3*i+1]; f2 = fdc[3*i+2];
        sc0 = scaling[3*i+0]; sc1 = scaling[3*i+1]; sc2 = scaling[3*i+2];
        ov  = opacity[i];
        q   = rotation[i];
    }
    const float cx = campos[0], cy = campos[1], cz = campos[2];
    const float mod = smod[0];

    // ---- early stores: pass-through + opacity + covariance ------------------
    // (independent of smem; overlap with the cp.async drain below)
    if (act) {
        out[3*i+0] = px; out[3*i+1] = py; out[3*i+2] = pz;
        out[(size_t)3*n + i] = 1.0f / (1.0f + expf(-ov));

        float s0 = expf(sc0) * mod;
        float s1 = expf(sc1) * mod;
        float s2 = expf(sc2) * mod;
        const float v0 = s0*s0, v1 = s1*s1, v2 = s2*s2;

        float qn = rsqrtf(q.x*q.x + q.y*q.y + q.z*q.z + q.w*q.w);
        const float w_ = q.x*qn, qx = q.y*qn, qy = q.z*qn, qz = q.w*qn;

        const float r00 = 1.0f - 2.0f*(qy*qy + qz*qz);
        const float r01 = 2.0f*(qx*qy - w_*qz);
        const float r02 = 2.0f*(qx*qz + w_*qy);
        const float r10 = 2.0f*(qx*qy + w_*qz);
        const float r11 = 1.0f - 2.0f*(qx*qx + qz*qz);
        const float r12 = 2.0f*(qy*qz - w_*qx);
        const float r20 = 2.0f*(qx*qz - w_*qy);
        const float r21 = 2.0f*(qy*qz + w_*qx);
        const float r22 = 1.0f - 2.0f*(qx*qx + qy*qy);

        const float m00 = r00*r00*v0 + r01*r01*v1 + r02*r02*v2;
        const float m01 = r00*r10*v0 + r01*r11*v1 + r02*r12*v2;
        const float m02 = r00*r20*v0 + r01*r21*v1 + r02*r22*v2;
        const float m11 = r10*r10*v0 + r11*r11*v1 + r12*r12*v2;
        const float m12 = r10*r20*v0 + r11*r21*v1 + r12*r22*v2;
        const float m22 = r20*r20*v0 + r21*r21*v1 + r22*r22*v2;

        const size_t covb = (size_t)7*n + (size_t)6*i;
        out[covb+0] = m00; out[covb+1] = m01; out[covb+2] = m02;
        out[covb+3] = m11; out[covb+4] = m12; out[covb+5] = m22;
    }

    // ---- per-warp wait: no cross-warp coupling ------------------------------
    if (full) {
        asm volatile("cp.async.wait_group 0;" ::: "memory");
        __syncwarp();
    } else {
        __syncthreads();
    }

    // ---- color (needs this warp's smem chunk only) --------------------------
    if (act) {
        float dx = px - cx, dy = py - cy, dz = pz - cz;
        float inv = rsqrtf(dx*dx + dy*dy + dz*dz);
        float x = dx * inv, y = dy * inv, z = dz * inv;

        const float xx = x*x, yy = y*y, zz = z*z;
        const float xy = x*y, yz = y*z, xz = x*z;

        float b[16];
        b[0]  = C0;
        b[1]  = -C1 * y;
        b[2]  =  C1 * z;
        b[3]  = -C1 * x;
        b[4]  = C2_0 * xy;
        b[5]  = C2_1 * yz;
        b[6]  = C2_2 * (2.0f*zz - xx - yy);
        b[7]  = C2_3 * xz;
        b[8]  = C2_4 * (xx - yy);
        b[9]  = C3_0 * y * (3.0f*xx - yy);
        b[10] = C3_1 * xy * z;
        b[11] = C3_2 * y * (4.0f*zz - xx - yy);
        b[12] = C3_3 * z * (2.0f*zz - 3.0f*xx - 3.0f*yy);
        b[13] = C3_4 * x * (4.0f*zz - xx - yy);
        b[14] = C3_5 * z * (xx - yy);
        b[15] = C3_6 * x * (xx - 3.0f*yy);

        float c0 = b[0] * f0;
        float c1 = b[0] * f1;
        float c2 = b[0] * f2;

        const float* fr = sbuf + tid * 45;   // stride 45: conflict-free
        #pragma unroll
        for (int k = 1; k < 16; ++k) {
            const float w = b[k];
            c0 = fmaf(w, fr[(k-1)*3 + 0], c0);
            c1 = fmaf(w, fr[(k-1)*3 + 1], c1);
            c2 = fmaf(w, fr[(k-1)*3 + 2], c2);
        }
        c0 = fmaxf(c0 + 0.5f, 0.0f);
        c1 = fmaxf(c1 + 0.5f, 0.0f);
        c2 = fmaxf(c2 + 0.5f, 0.0f);

        // direct stores: stride-3 across the warp = 3 fully-covered 128B lines
        const size_t colb = (size_t)4*n;
        out[colb + 3*i+0] = c0;
        out[colb + 3*i+1] = c1;
        out[colb + 3*i+2] = c2;
    }
}

extern "C" void kernel_launch(void* const* d_in, const int* in_sizes, int n_in,
                              void* d_out, int out_size) {
    const float*  xyz      = (const float*)d_in[0];
    const float*  fdc      = (const float*)d_in[1];
    const float*  frest    = (const float*)d_in[2];
    const float*  scaling  = (const float*)d_in[3];
    const float4* rotation = (const float4*)d_in[4];
    const float*  opacity  = (const float*)d_in[5];
    const float*  campos   = (const float*)d_in[6];
    const float*  smod     = (const float*)d_in[7];
    float* out = (float*)d_out;

    const int n = in_sizes[0] / 3;

    const int grid = (n + BLK - 1) / BLK;
    gs_preprocess_kernel<<<grid, BLK>>>(xyz, fdc, frest, scaling, rotation,
                                        opacity, campos, smod, out, n);
}

// round 16
// speedup vs baseline: 1.0051x; 1.0025x over previous
#include <cuda_runtime.h>
#include <cstdint>

#define C0  0.28209479177387814f
#define C1  0.4886025119029199f
#define C2_0  1.0925484305920792f
#define C2_1 (-1.0925484305920792f)
#define C2_2  0.31539156525252005f
#define C2_3 (-1.0925484305920792f)
#define C2_4  0.5462742152960396f
#define C3_0 (-0.5900435899266435f)
#define C3_1  2.890611442640554f
#define C3_2 (-0.4570457994644658f)
#define C3_3  0.3731763325901154f
#define C3_4 (-0.4570457994644658f)
#define C3_5  1.445305721320277f
#define C3_6 (-0.5900435899266435f)

#define BLK 256
#define FR_FLOATS (BLK * 45)          // 11520 floats = 45 KB
#define WARP_F4  360                  // 32 rows * 45 floats / 4 per warp

__device__ __forceinline__ uint32_t smem_u32(const void* p) {
    uint32_t a;
    asm("{ .reg .u64 t; cvta.to.shared.u64 t, %1; cvt.u32.u64 %0, t; }"
        : "=r"(a) : "l"(p));
    return a;
}

__global__ __launch_bounds__(BLK)
void gs_preprocess_kernel(const float*  __restrict__ xyz,
                          const float*  __restrict__ fdc,
                          const float*  __restrict__ frest,
                          const float*  __restrict__ scaling,
                          const float4* __restrict__ rotation,
                          const float*  __restrict__ opacity,
                          const float*  __restrict__ campos,
                          const float*  __restrict__ smod,
                          float* __restrict__ out,
                          int n)
{
    __shared__ float sbuf[FR_FLOATS];

    const int tid  = threadIdx.x;
    const int wid  = tid >> 5;
    const int lane = tid & 31;
    const int base = blockIdx.x * BLK;
    const int i    = base + tid;
    const bool full = (base + BLK <= n);
    const bool act  = (i < n);

    // ---- warp-private staging: each warp copies ONLY its own 32 rows --------
    if (full) {
        // warp chunk: rows [base + wid*32, +32), 5760 B, 16B-aligned
        const float4* g = (const float4*)(frest + ((size_t)base + wid * 32) * 45);
        const uint32_t s0 = smem_u32(sbuf + wid * (32 * 45));
        #pragma unroll
        for (int j = lane; j < WARP_F4; j += 32) {
            asm volatile("cp.async.cg.shared.global [%0], [%1], 16;"
                         :: "r"(s0 + j * 16), "l"(g + j) : "memory");
        }
        asm volatile("cp.async.commit_group;" ::: "memory");
    } else {
        const int cnt = (n - base) * 45;
        for (int j = tid; j < cnt; j += BLK)
            sbuf[j] = frest[(size_t)base * 45 + j];
    }

    // ---- front-batch scalar inputs: fly concurrently with the staging -------
    float px=0, py=0, pz=0;
    float f0=0, f1=0, f2=0;
    float sc0=0, sc1=0, sc2=0;
    float ov=0;
    float4 q = make_float4(1,0,0,0);
    if (act) {
        px  = xyz[3*i+0]; py = xyz[3*i+1]; pz = xyz[3*i+2];
        f0  = fdc[3*i+0]; f1 = fdc[3*i+1]; f2 = fdc[3*i+2];
        sc0 = scaling[3*i+0]; sc1 = scaling[3*i+1]; sc2 = scaling[3*i+2];
        ov  = opacity[i];
        q   = rotation[i];
    }
    const float cx = campos[0], cy = campos[1], cz = campos[2];
    const float mod = smod[0];

    // ---- early stores: pass-through + opacity + covariance ------------------
    // (independent of smem; overlap with the cp.async drain below)
    if (act) {
        out[3*i+0] = px; out[3*i+1] = py; out[3*i+2] = pz;
        out[(size_t)3*n + i] = 1.0f / (1.0f + expf(-ov));

        float s0 = expf(sc0) * mod;
        float s1 = expf(sc1) * mod;
        float s2 = expf(sc2) * mod;
        const float v0 = s0*s0, v1 = s1*s1, v2 = s2*s2;

        float qn = rsqrtf(q.x*q.x + q.y*q.y + q.z*q.z + q.w*q.w);
        const float w_ = q.x*qn, qx = q.y*qn, qy = q.z*qn, qz = q.w*qn;

        const float r00 = 1.0f - 2.0f*(qy*qy + qz*qz);
        const float r01 = 2.0f*(qx*qy - w_*qz);
        const float r02 = 2.0f*(qx*qz + w_*qy);
        const float r10 = 2.0f*(qx*qy + w_*qz);
        const float r11 = 1.0f - 2.0f*(qx*qx + qz*qz);
        const float r12 = 2.0f*(qy*qz - w_*qx);
        const float r20 = 2.0f*(qx*qz - w_*qy);
        const float r21 = 2.0f*(qy*qz + w_*qx);
        const float r22 = 1.0f - 2.0f*(qx*qx + qy*qy);

        const float m00 = r00*r00*v0 + r01*r01*v1 + r02*r02*v2;
        const float m01 = r00*r10*v0 + r01*r11*v1 + r02*r12*v2;
        const float m02 = r00*r20*v0 + r01*r21*v1 + r02*r22*v2;
        const float m11 = r10*r10*v0 + r11*r11*v1 + r12*r12*v2;
        const float m12 = r10*r20*v0 + r11*r21*v1 + r12*r22*v2;
        const float m22 = r20*r20*v0 + r21*r21*v1 + r22*r22*v2;

        const size_t covb = (size_t)7*n + (size_t)6*i;
        out[covb+0] = m00; out[covb+1] = m01; out[covb+2] = m02;
        out[covb+3] = m11; out[covb+4] = m12; out[covb+5] = m22;
    }

    // ---- per-warp wait: no cross-warp coupling ------------------------------
    if (full) {
        asm volatile("cp.async.wait_group 0;" ::: "memory");
        __syncwarp();
    } else {
        __syncthreads();
    }

    // ---- color (needs this warp's smem chunk only) --------------------------
    if (act) {
        float dx = px - cx, dy = py - cy, dz = pz - cz;
        float inv = rsqrtf(dx*dx + dy*dy + dz*dz);
        float x = dx * inv, y = dy * inv, z = dz * inv;

        const float xx = x*x, yy = y*y, zz = z*z;
        const float xy = x*y, yz = y*z, xz = x*z;

        float b[16];
        b[0]  = C0;
        b[1]  = -C1 * y;
        b[2]  =  C1 * z;
        b[3]  = -C1 * x;
        b[4]  = C2_0 * xy;
        b[5]  = C2_1 * yz;
        b[6]  = C2_2 * (2.0f*zz - xx - yy);
        b[7]  = C2_3 * xz;
        b[8]  = C2_4 * (xx - yy);
        b[9]  = C3_0 * y * (3.0f*xx - yy);
        b[10] = C3_1 * xy * z;
        b[11] = C3_2 * y * (4.0f*zz - xx - yy);
        b[12] = C3_3 * z * (2.0f*zz - 3.0f*xx - 3.0f*yy);
        b[13] = C3_4 * x * (4.0f*zz - xx - yy);
        b[14] = C3_5 * z * (xx - yy);
        b[15] = C3_6 * x * (xx - 3.0f*yy);

        float c0 = b[0] * f0;
        float c1 = b[0] * f1;
        float c2 = b[0] * f2;

        const float* fr = sbuf + tid * 45;   // stride 45: conflict-free
        #pragma unroll
        for (int k = 1; k < 16; ++k) {
            const float w = b[k];
            c0 = fmaf(w, fr[(k-1)*3 + 0], c0);
            c1 = fmaf(w, fr[(k-1)*3 + 1], c1);
            c2 = fmaf(w, fr[(k-1)*3 + 2], c2);
        }
        c0 = fmaxf(c0 + 0.5f, 0.0f);
        c1 = fmaxf(c1 + 0.5f, 0.0f);
        c2 = fmaxf(c2 + 0.5f, 0.0f);

        // direct stores: stride-3 across the warp = 3 fully-covered 128B lines
        const size_t colb = (size_t)4*n;
        out[colb + 3*i+0] = c0;
        out[colb + 3*i+1] = c1;
        out[colb + 3*i+2] = c2;
    }
}

extern "C" void kernel_launch(void* const* d_in, const int* in_sizes, int n_in,
                              void* d_out, int out_size) {
    const float*  xyz      = (const float*)d_in[0];
    const float*  fdc      = (const float*)d_in[1];
    const float*  frest    = (const float*)d_in[2];
    const float*  scaling  = (const float*)d_in[3];
    const float4* rotation = (const float4*)d_in[4];
    const float*  opacity  = (const float*)d_in[5];
    const float*  campos   = (const float*)d_in[6];
    const float*  smod     = (const float*)d_in[7];
    float* out = (float*)d_out;

    const int n = in_sizes[0] / 3;

    const int grid = (n + BLK - 1) / BLK;
    gs_preprocess_kernel<<<grid, BLK>>>(xyz, fdc, frest, scaling, rotation,
                                        opacity, campos, smod, out, n);
}